// round 1
// baseline (speedup 1.0000x reference)
#include <cuda_runtime.h>
#include <math.h>

#define BATCH 256
#define N0 400
#define N1 200
#define N2 100
#define NT 50
#define NP 56      // padded col count for M / Y
#define LD 51      // smem leading dim (odd -> conflict-free column access)
#define NSWEEP 8
#define NFEAT 1275

__device__ __align__(16) float g_T[N1 * NT];                 // W2@W3  (200x50)
__device__ __align__(16) float g_M[N0 * NP];                 // W1@W2@W3 padded (400x56)
__device__ __align__(16) float g_Y[(size_t)BATCH * N0 * NP]; // X@M    (256x400x56)

// ---------------- K1a: T = W2 @ W3 ----------------
__global__ void k_w2w3(const float* __restrict__ W2, const float* __restrict__ W3) {
    int stride = gridDim.x * blockDim.x;
    for (int t = blockIdx.x * blockDim.x + threadIdx.x; t < N1 * NT; t += stride) {
        int i = t / NT, j = t - (t / NT) * NT;
        float acc = 0.f;
        for (int k = 0; k < N2; k++) acc += W2[i * N2 + k] * W3[k * NT + j];
        g_T[t] = acc;
    }
}

// ---------------- K1b: M = W1 @ T (zero-padded to 56 cols) ----------------
__global__ void k_w1t(const float* __restrict__ W1) {
    int stride = gridDim.x * blockDim.x;
    for (int t = blockIdx.x * blockDim.x + threadIdx.x; t < N0 * NP; t += stride) {
        int i = t / NP, j = t - (t / NP) * NP;
        float acc = 0.f;
        if (j < NT) {
            for (int k = 0; k < N1; k++) acc += W1[i * N1 + k] * g_T[k * NT + j];
        }
        g_M[t] = acc;
    }
}

// ---------------- K2: Y[b] = X[b] @ M  (400x400 @ 400x56) ----------------
// Block tile: 80 rows x 56 cols, 224 threads (14x16), microtile 5x4, K-chunk 16.
__global__ __launch_bounds__(224) void k_xm(const float* __restrict__ X) {
    __shared__ float Xs[80][16];
    __shared__ float Ms[16][NP];
    int b = blockIdx.y;
    int row0 = blockIdx.x * 80;
    int tx = threadIdx.x;  // 0..13 -> 4 cols each
    int ty = threadIdx.y;  // 0..15 -> 5 rows each
    int tid = ty * 14 + tx;
    const float* Xb = X + (size_t)b * N0 * N0;
    float* Yb = g_Y + (size_t)b * N0 * NP;
    float acc[5][4] = {};
    for (int kc = 0; kc < N0; kc += 16) {
        // load Xs: 80x16 = 320 float4
        for (int l = tid; l < 320; l += 224) {
            int r = l >> 2, c4 = (l & 3) << 2;
            *(float4*)&Xs[r][c4] =
                *(const float4*)(Xb + (size_t)(row0 + r) * N0 + kc + c4);
        }
        // load Ms: 16x56 = 224 float4, exactly one per thread
        {
            int r = tid / 14, c4 = (tid - (tid / 14) * 14) << 2;
            *(float4*)&Ms[r][c4] = *(const float4*)(g_M + (kc + r) * NP + c4);
        }
        __syncthreads();
#pragma unroll
        for (int k = 0; k < 16; k++) {
            float4 bv = *(float4*)&Ms[k][tx << 2];
#pragma unroll
            for (int r = 0; r < 5; r++) {
                float a = Xs[ty * 5 + r][k];
                acc[r][0] += a * bv.x;
                acc[r][1] += a * bv.y;
                acc[r][2] += a * bv.z;
                acc[r][3] += a * bv.w;
            }
        }
        __syncthreads();
    }
#pragma unroll
    for (int r = 0; r < 5; r++) {
        float4 v = make_float4(acc[r][0], acc[r][1], acc[r][2], acc[r][3]);
        *(float4*)(Yb + (size_t)(row0 + ty * 5 + r) * NP + (tx << 2)) = v;
    }
}

// map linear upper-triangular index t (triu_indices(50) row-major) -> (i,j)
__device__ __forceinline__ void tri_ij(int t, int& i, int& j) {
    int ii = (int)((101.0f - sqrtf(10201.0f - 8.0f * (float)t)) * 0.5f);
    if (ii < 0) ii = 0;
    if (ii > 49) ii = 49;
    while (ii > 0 && ii * (101 - ii) / 2 > t) ii--;
    while (ii < 49 && (ii + 1) * (100 - ii) / 2 <= t) ii++;
    i = ii;
    j = ii + t - ii * (101 - ii) / 2;
}

// ---------------- K3: per-batch  h = M^T Y, Jacobi eig, log-map, head ----------------
__global__ __launch_bounds__(256) void k_eig(const float* __restrict__ Wl,
                                             const float* __restrict__ bl,
                                             float* __restrict__ out) {
    __shared__ float sA[NT * LD];   // h, then rotated to diagonal
    __shared__ float sV[64 * LD];   // M-tile during h-compute, then eigenvectors V
    __shared__ float sY[64 * LD];   // Y-tile during h-compute, then Vl = V*diag(log w)
    __shared__ float s_c[25], s_s[25];
    __shared__ int s_p[25], s_q[25];
    __shared__ float s_lw[NT];
    __shared__ float s_red[7 * 8];

    int b = blockIdx.x;
    int tid = threadIdx.x;
    const float* Yb = g_Y + (size_t)b * N0 * NP;

    // ---- h = M^T Y : thread (tid<250) owns a 2x5 output microtile ----
    float hacc[2][5] = {};
    int i0 = 2 * (tid / 10), j0 = 5 * (tid % 10);
    for (int kc = 0; kc < N0; kc += 64) {
        for (int l = tid; l < 64 * NT; l += 256) {
            int r = l / NT, c = l - (l / NT) * NT;
            int gk = kc + r;
            float yv = 0.f, mv = 0.f;
            if (gk < N0) {
                yv = Yb[gk * NP + c];
                mv = g_M[gk * NP + c];
            }
            sY[r * LD + c] = yv;
            sV[r * LD + c] = mv;
        }
        __syncthreads();
        if (tid < 250) {
            for (int k = 0; k < 64; k++) {
                float m0 = sV[k * LD + i0], m1 = sV[k * LD + i0 + 1];
#pragma unroll
                for (int j = 0; j < 5; j++) {
                    float y = sY[k * LD + j0 + j];
                    hacc[0][j] += m0 * y;
                    hacc[1][j] += m1 * y;
                }
            }
        }
        __syncthreads();
    }
    if (tid < 250) {
#pragma unroll
        for (int j = 0; j < 5; j++) {
            sA[i0 * LD + j0 + j] = hacc[0][j];
            sA[(i0 + 1) * LD + j0 + j] = hacc[1][j];
        }
    }
    __syncthreads();
    // symmetrize (kills ~1e-7 fp asymmetry)
    for (int t = tid; t < NFEAT; t += 256) {
        int i, j;
        tri_ij(t, i, j);
        if (i < j) {
            float v = 0.5f * (sA[i * LD + j] + sA[j * LD + i]);
            sA[i * LD + j] = v;
            sA[j * LD + i] = v;
        }
    }
    // V = I
    for (int l = tid; l < NT * LD; l += 256) sV[l] = 0.f;
    __syncthreads();
    if (tid < NT) sV[tid * LD + tid] = 1.f;
    __syncthreads();

    // ---- parallel cyclic Jacobi: 25 disjoint rotations/round, 49 rounds/sweep ----
    for (int sw = 0; sw < NSWEEP; sw++) {
        for (int r = 0; r < 49; r++) {
            if (tid < 25) {
                int p, q;
                if (tid == 0) {
                    p = r % 49;
                    q = 49;
                } else {
                    p = (r + tid) % 49;
                    q = (r + 49 - tid) % 49;
                    if (p > q) { int tmp = p; p = q; q = tmp; }
                }
                float app = sA[p * LD + p], aqq = sA[q * LD + q], apq = sA[p * LD + q];
                float c = 1.f, s = 0.f;
                if (fabsf(apq) > 1e-30f) {
                    float tau = (aqq - app) / (2.f * apq);
                    float tt = copysignf(1.f, tau) / (fabsf(tau) + sqrtf(1.f + tau * tau));
                    c = rsqrtf(1.f + tt * tt);
                    s = tt * c;
                }
                s_c[tid] = c;
                s_s[tid] = s;
                s_p[tid] = p;
                s_q[tid] = q;
            }
            __syncthreads();
            // A: 625 fused 2x2-block items (pair_a rows x pair_b cols); V: 1250 items
            for (int it = tid; it < 625 + 1250; it += 256) {
                if (it < 625) {
                    int a = it / 25, e = it - a * 25;
                    int pa = s_p[a], qa = s_q[a];
                    float ca = s_c[a], sa = s_s[a];
                    int pb = s_p[e], qb = s_q[e];
                    float cb = s_c[e], sb = s_s[e];
                    float App = sA[pa * LD + pb], Apq = sA[pa * LD + qb];
                    float Aqp = sA[qa * LD + pb], Aqq = sA[qa * LD + qb];
                    float t0 = cb * App - sb * Apq, t1 = sb * App + cb * Apq;
                    float t2 = cb * Aqp - sb * Aqq, t3 = sb * Aqp + cb * Aqq;
                    sA[pa * LD + pb] = ca * t0 - sa * t2;
                    sA[pa * LD + qb] = ca * t1 - sa * t3;
                    sA[qa * LD + pb] = sa * t0 + ca * t2;
                    sA[qa * LD + qb] = sa * t1 + ca * t3;
                } else {
                    int iv = it - 625;
                    int a = iv / 50, i = iv - a * 50;
                    int p = s_p[a], q = s_q[a];
                    float ca = s_c[a], sa = s_s[a];
                    float vp = sV[i * LD + p], vq = sV[i * LD + q];
                    sV[i * LD + p] = ca * vp - sa * vq;
                    sV[i * LD + q] = sa * vp + ca * vq;
                }
            }
            __syncthreads();
        }
    }

    // ---- eigenvalue logs, Vl = V*diag(log w) ----
    if (tid < NT) s_lw[tid] = logf(fmaxf(sA[tid * LD + tid], 1e-4f));
    __syncthreads();
    for (int l = tid; l < NT * NT; l += 256) {
        int i = l / NT, k = l - (l / NT) * NT;
        sY[i * LD + k] = sV[i * LD + k] * s_lw[k];
    }
    __syncthreads();

    // ---- feat (1275) fused into the 7-dim head, deterministic reduction ----
    float po[7] = {0, 0, 0, 0, 0, 0, 0};
    for (int t = tid; t < NFEAT; t += 256) {
        int i, j;
        tri_ij(t, i, j);
        float s = 0.f;
        for (int k = 0; k < NT; k++) s += sY[i * LD + k] * sV[j * LD + k];
        float f = (i == j) ? s : s * 1.41421356237f;
#pragma unroll
        for (int c = 0; c < 7; c++) po[c] += f * Wl[c * NFEAT + t];
    }
    int lane = tid & 31, warp = tid >> 5;
#pragma unroll
    for (int off = 16; off > 0; off >>= 1) {
#pragma unroll
        for (int c = 0; c < 7; c++) po[c] += __shfl_down_sync(0xffffffffu, po[c], off);
    }
    if (lane == 0) {
#pragma unroll
        for (int c = 0; c < 7; c++) s_red[c * 8 + warp] = po[c];
    }
    __syncthreads();
    if (tid < 7) {
        float sum = bl[tid];
#pragma unroll
        for (int w = 0; w < 8; w++) sum += s_red[tid * 8 + w];
        out[b * 7 + tid] = sum;
    }
}

extern "C" void kernel_launch(void* const* d_in, const int* in_sizes, int n_in,
                              void* d_out, int out_size) {
    const float* x  = (const float*)d_in[0];
    const float* W1 = (const float*)d_in[1];
    const float* W2 = (const float*)d_in[2];
    const float* W3 = (const float*)d_in[3];
    const float* Wl = (const float*)d_in[4];
    const float* bl = (const float*)d_in[5];
    float* out = (float*)d_out;

    k_w2w3<<<40, 256>>>(W2, W3);
    k_w1t<<<88, 256>>>(W1);
    k_xm<<<dim3(5, BATCH), dim3(14, 16)>>>(x);
    k_eig<<<BATCH, 256>>>(Wl, bl, out);
}

// round 2
// speedup vs baseline: 2.5994x; 2.5994x over previous
#include <cuda_runtime.h>
#include <math.h>

#define BATCH 256
#define N0 400
#define N1 200
#define N2 100
#define NT 50
#define NP 56      // padded col count for M / Y
#define LD 51      // smem leading dim (odd -> conflict-free column access)
#define NFEAT 1275
#define CHEB_D 14  // Chebyshev degree for matrix log

__device__ __align__(16) float g_T[N1 * NT];                 // W2@W3  (200x50)
__device__ __align__(16) float g_M[N0 * NP];                 // W1@W2@W3 padded (400x56)
__device__ __align__(16) float g_Y[(size_t)BATCH * N0 * NP]; // X@M    (256x400x56)

// packed dual-fp32 FMA (ptxas never emits FFMA2 from C++; must come from PTX)
__device__ __forceinline__ void ffma2(float2& d, float2 a, float2 b) {
    asm("fma.rn.f32x2 %0, %1, %2, %0;"
        : "+l"(*reinterpret_cast<unsigned long long*>(&d))
        : "l"(*reinterpret_cast<unsigned long long*>(&a)),
          "l"(*reinterpret_cast<unsigned long long*>(&b)));
}

// ---------------- K1a: T = W2 @ W3 ----------------
__global__ void k_w2w3(const float* __restrict__ W2, const float* __restrict__ W3) {
    int stride = gridDim.x * blockDim.x;
    for (int t = blockIdx.x * blockDim.x + threadIdx.x; t < N1 * NT; t += stride) {
        int i = t / NT, j = t - (t / NT) * NT;
        float acc = 0.f;
        for (int k = 0; k < N2; k++) acc += W2[i * N2 + k] * W3[k * NT + j];
        g_T[t] = acc;
    }
}

// ---------------- K1b: M = W1 @ T (zero-padded to 56 cols) ----------------
__global__ void k_w1t(const float* __restrict__ W1) {
    int stride = gridDim.x * blockDim.x;
    for (int t = blockIdx.x * blockDim.x + threadIdx.x; t < N0 * NP; t += stride) {
        int i = t / NP, j = t - (t / NP) * NP;
        float acc = 0.f;
        if (j < NT) {
            for (int k = 0; k < N1; k++) acc += W1[i * N1 + k] * g_T[k * NT + j];
        }
        g_M[t] = acc;
    }
}

// ---------------- K2: Y[b] = X[b] @ M  (400x400 @ 400x56) ----------------
// Block tile: 80 rows x 56 cols, 224 threads (14x16), microtile 5x4 via f32x2.
__global__ __launch_bounds__(224) void k_xm(const float* __restrict__ X) {
    __shared__ float Xs[80][16];
    __shared__ float Ms[16][NP];
    int b = blockIdx.y;
    int row0 = blockIdx.x * 80;
    int tx = threadIdx.x;  // 0..13 -> 4 cols each
    int ty = threadIdx.y;  // 0..15 -> 5 rows each
    int tid = ty * 14 + tx;
    const float* Xb = X + (size_t)b * N0 * N0;
    float* Yb = g_Y + (size_t)b * N0 * NP;
    float2 acc[5][2] = {};
    for (int kc = 0; kc < N0; kc += 16) {
        for (int l = tid; l < 320; l += 224) {
            int r = l >> 2, c4 = (l & 3) << 2;
            *(float4*)&Xs[r][c4] =
                *(const float4*)(Xb + (size_t)(row0 + r) * N0 + kc + c4);
        }
        {
            int r = tid / 14, c4 = (tid - (tid / 14) * 14) << 2;
            *(float4*)&Ms[r][c4] = *(const float4*)(g_M + (kc + r) * NP + c4);
        }
        __syncthreads();
#pragma unroll
        for (int k = 0; k < 16; k++) {
            float2 bv0 = *(float2*)&Ms[k][tx << 2];
            float2 bv1 = *(float2*)&Ms[k][(tx << 2) + 2];
#pragma unroll
            for (int r = 0; r < 5; r++) {
                float a = Xs[ty * 5 + r][k];
                float2 aa = make_float2(a, a);
                ffma2(acc[r][0], aa, bv0);
                ffma2(acc[r][1], aa, bv1);
            }
        }
        __syncthreads();
    }
#pragma unroll
    for (int r = 0; r < 5; r++) {
        float4 v = make_float4(acc[r][0].x, acc[r][0].y, acc[r][1].x, acc[r][1].y);
        *(float4*)(Yb + (size_t)(row0 + ty * 5 + r) * NP + (tx << 2)) = v;
    }
}

// map linear upper-triangular index t (triu_indices(50) row-major) -> (i,j)
__device__ __forceinline__ void tri_ij(int t, int& i, int& j) {
    int ii = (int)((101.0f - sqrtf(10201.0f - 8.0f * (float)t)) * 0.5f);
    if (ii < 0) ii = 0;
    if (ii > 49) ii = 49;
    while (ii > 0 && ii * (101 - ii) / 2 > t) ii--;
    while (ii < 49 && (ii + 1) * (100 - ii) / 2 <= t) ii++;
    i = ii;
    j = ii + t - ii * (101 - ii) / 2;
}

// ---------------- K3: h = M^T Y, S = log(h) via Chebyshev/Clenshaw, head ----------------
// 512 threads, 2 batches per block (one per 256-thread half). Grid 128 -> one wave.
// Per-half smem: sH (Ts, 50x51), sB1, sB2 (Clenshaw state; double as M/Y staging).
#define HALF_F (3 * NT * LD + 18)  // +pad
__global__ __launch_bounds__(512) void k_poly(const float* __restrict__ Wl,
                                              const float* __restrict__ bl,
                                              float* __restrict__ out) {
    extern __shared__ float smem[];
    __shared__ float s_r[2][64];
    __shared__ float s_bb[2];
    __shared__ float s_red[2][7 * 8];

    int half = threadIdx.x >> 8;
    int tid = threadIdx.x & 255;
    int b = blockIdx.x * 2 + half;

    float* sH = smem + half * HALF_F;          // h, then Ts
    float* sB1 = sH + NT * LD;                 // Clenshaw B_{k+1}; staging M-tile
    float* sB2 = sB1 + NT * LD;                // Clenshaw B_{k+2}; staging Y-tile

    const float* Yb = g_Y + (size_t)b * N0 * NP;

    // ---- h = M^T Y : thread owns 2x5 tile; K staged in 50-row chunks ----
    float hacc[2][5] = {};
    int i0 = 2 * (tid / 10), j0 = 5 * (tid % 10);
    for (int kc = 0; kc < N0; kc += NT) {
        for (int l = tid; l < NT * NT; l += 256) {
            int r = l / NT, c = l - (l / NT) * NT;
            sB1[r * LD + c] = g_M[(kc + r) * NP + c];
            sB2[r * LD + c] = Yb[(kc + r) * NP + c];
        }
        __syncthreads();
        if (tid < 250) {
#pragma unroll 5
            for (int k = 0; k < NT; k++) {
                float m0 = sB1[k * LD + i0], m1 = sB1[k * LD + i0 + 1];
#pragma unroll
                for (int j = 0; j < 5; j++) {
                    float y = sB2[k * LD + j0 + j];
                    hacc[0][j] += m0 * y;
                    hacc[1][j] += m1 * y;
                }
            }
        }
        __syncthreads();
    }
    if (tid < 250) {
#pragma unroll
        for (int j = 0; j < 5; j++) {
            sH[i0 * LD + j0 + j] = hacc[0][j];
            sH[(i0 + 1) * LD + j0 + j] = hacc[1][j];
        }
    }
    __syncthreads();

    // ---- Gershgorin upper bound b, fixed lower bound a (spectrum >= 1 by construction) ----
    if (tid < NT) {
        float s = 0.f;
        for (int j = 0; j < NT; j++) s += fabsf(sH[tid * LD + j]);
        s_r[half][tid] = s;
    }
    __syncthreads();
    if (tid == 0) {
        float mx = 0.f;
        for (int i = 0; i < NT; i++) mx = fmaxf(mx, s_r[half][i]);
        s_bb[half] = mx;
    }
    __syncthreads();
    float aa = 0.95f, bb = s_bb[half];
    float mid = 0.5f * (aa + bb);
    float kap = (bb - aa) / (bb + aa);
    float z = (1.f - sqrtf(fmaxf(1.f - kap * kap, 0.f))) / kap;
    float c0 = logf(mid) - logf(1.f + z * z);

    // ---- Ts = (2h - (a+b)I) / (b-a), in place ----
    {
        float inv = 1.f / (bb - aa);
        for (int l = tid; l < NT * NT; l += 256) {
            int i = l / NT, j = l - (l / NT) * NT;
            float v = (2.f * sH[i * LD + j] - (i == j ? (aa + bb) : 0.f)) * inv;
            sH[i * LD + j] = v;
        }
        // zero Clenshaw state
        for (int l = tid; l < NT * NT; l += 256) {
            int i = l / NT, j = l - (l / NT) * NT;
            sB1[i * LD + j] = 0.f;
            sB2[i * LD + j] = 0.f;
        }
    }
    __syncthreads();

    // ---- Clenshaw: B_k = c_k I + 2 Ts B_{k+1} - B_{k+2} ; S = c0 I + Ts B_1 - B_2 ----
    float* pb1 = sB1;
    float* pb2 = sB2;
    for (int k = CHEB_D; k >= 1; k--) {
        float ck = 2.f * __powf(z, (float)k) / (float)k;
        if (!(k & 1)) ck = -ck;
        if (tid < 250) {
            float p[2][5] = {};
#pragma unroll 5
            for (int kk = 0; kk < NT; kk++) {
                float t0 = sH[i0 * LD + kk], t1 = sH[(i0 + 1) * LD + kk];
#pragma unroll
                for (int j = 0; j < 5; j++) {
                    float bv = pb1[kk * LD + j0 + j];
                    p[0][j] += t0 * bv;
                    p[1][j] += t1 * bv;
                }
            }
#pragma unroll
            for (int r = 0; r < 2; r++) {
                int i = i0 + r;
#pragma unroll
                for (int j = 0; j < 5; j++) {
                    int jj = j0 + j;
                    float nv = 2.f * p[r][j] - pb2[i * LD + jj];
                    if (i == jj) nv += ck;
                    pb2[i * LD + jj] = nv;
                }
            }
        }
        __syncthreads();
        float* tmp = pb1; pb1 = pb2; pb2 = tmp;
    }
    // final: S = c0 I + Ts B1 - B2  -> into pb2
    if (tid < 250) {
        float p[2][5] = {};
#pragma unroll 5
        for (int kk = 0; kk < NT; kk++) {
            float t0 = sH[i0 * LD + kk], t1 = sH[(i0 + 1) * LD + kk];
#pragma unroll
            for (int j = 0; j < 5; j++) {
                float bv = pb1[kk * LD + j0 + j];
                p[0][j] += t0 * bv;
                p[1][j] += t1 * bv;
            }
        }
#pragma unroll
        for (int r = 0; r < 2; r++) {
            int i = i0 + r;
#pragma unroll
            for (int j = 0; j < 5; j++) {
                int jj = j0 + j;
                float nv = p[r][j] - pb2[i * LD + jj];
                if (i == jj) nv += c0;
                pb2[i * LD + jj] = nv;
            }
        }
    }
    __syncthreads();
    float* S = pb2;

    // ---- feat (1275 upper-tri, sqrt2 off-diag) fused into 7-dim head ----
    float po[7] = {0, 0, 0, 0, 0, 0, 0};
    for (int t = tid; t < NFEAT; t += 256) {
        int i, j;
        tri_ij(t, i, j);
        float s = S[i * LD + j];
        float f = (i == j) ? s : s * 1.41421356237f;
#pragma unroll
        for (int c = 0; c < 7; c++) po[c] += f * Wl[c * NFEAT + t];
    }
    int lane = tid & 31, warp = tid >> 5;
#pragma unroll
    for (int off = 16; off > 0; off >>= 1) {
#pragma unroll
        for (int c = 0; c < 7; c++) po[c] += __shfl_down_sync(0xffffffffu, po[c], off);
    }
    if (lane == 0) {
#pragma unroll
        for (int c = 0; c < 7; c++) s_red[half][c * 8 + warp] = po[c];
    }
    __syncthreads();
    if (tid < 7) {
        float sum = bl[tid];
#pragma unroll
        for (int w = 0; w < 8; w++) sum += s_red[half][tid * 8 + w];
        out[b * 7 + tid] = sum;
    }
}

extern "C" void kernel_launch(void* const* d_in, const int* in_sizes, int n_in,
                              void* d_out, int out_size) {
    const float* x  = (const float*)d_in[0];
    const float* W1 = (const float*)d_in[1];
    const float* W2 = (const float*)d_in[2];
    const float* W3 = (const float*)d_in[3];
    const float* Wl = (const float*)d_in[4];
    const float* bl = (const float*)d_in[5];
    float* out = (float*)d_out;

    static int smem_set = 0;
    int smem_bytes = 2 * HALF_F * (int)sizeof(float);
    if (!smem_set) {
        cudaFuncSetAttribute(k_poly, cudaFuncAttributeMaxDynamicSharedMemorySize,
                             smem_bytes);
        smem_set = 1;
    }

    k_w2w3<<<40, 256>>>(W2, W3);
    k_w1t<<<88, 256>>>(W1);
    k_xm<<<dim3(5, BATCH), dim3(14, 16)>>>(x);
    k_poly<<<BATCH / 2, 512, smem_bytes>>>(Wl, bl, out);
}

// round 3
// speedup vs baseline: 3.0993x; 1.1923x over previous
#include <cuda_runtime.h>
#include <math.h>

#define BATCH 256
#define N0 400
#define N1 200
#define N2 100
#define NT 50
#define NP 56      // col count for M / Y (no pad needed, 56 % 4 == 0)
#define LDA 51     // smem leading dim for Ts (odd)
#define LDB 52     // smem leading dim for Clenshaw buffers (even -> f32x2 aligned)
#define NFEAT 1275
#define CHEB_D 10  // Chebyshev degree for matrix log

#define KC 40      // K-chunk in k_xm
#define RT 64      // row tile in k_xm (4 rows x 16 row-groups)

__device__ __align__(16) float g_T[N1 * NT];                 // W2@W3  (200x50)
__device__ __align__(16) float g_M[N0 * NP];                 // W1@W2@W3 padded (400x56)
__device__ __align__(16) float g_Y[(size_t)BATCH * N0 * NP]; // X@M    (256x400x56)

// packed dual-fp32 FMA (ptxas never emits FFMA2 from C++; must come from PTX)
__device__ __forceinline__ void ffma2(float2& d, float2 a, float2 b) {
    asm("fma.rn.f32x2 %0, %1, %2, %0;"
        : "+l"(*reinterpret_cast<unsigned long long*>(&d))
        : "l"(*reinterpret_cast<unsigned long long*>(&a)),
          "l"(*reinterpret_cast<unsigned long long*>(&b)));
}

// ---------------- K1a: T = W2 @ W3 ----------------
__global__ void k_w2w3(const float* __restrict__ W2, const float* __restrict__ W3) {
    int stride = gridDim.x * blockDim.x;
    for (int t = blockIdx.x * blockDim.x + threadIdx.x; t < N1 * NT; t += stride) {
        int i = t / NT, j = t - (t / NT) * NT;
        float acc = 0.f;
        for (int k = 0; k < N2; k++) acc += W2[i * N2 + k] * W3[k * NT + j];
        g_T[t] = acc;
    }
}

// ---------------- K1b: M = W1 @ T (zero-padded to 56 cols) ----------------
__global__ void k_w1t(const float* __restrict__ W1) {
    int stride = gridDim.x * blockDim.x;
    for (int t = blockIdx.x * blockDim.x + threadIdx.x; t < N0 * NP; t += stride) {
        int i = t / NP, j = t - (t / NP) * NP;
        float acc = 0.f;
        if (j < NT) {
            for (int k = 0; k < N1; k++) acc += W1[i * N1 + k] * g_T[k * NT + j];
        }
        g_M[t] = acc;
    }
}

// ---------------- K2: Y[b] = X[b] @ M  (400x400 @ 400x56) ----------------
// Tile 64 rows x 56 cols, 224 threads, microtile 4x4 (f32x2), K-chunk 40.
// A-tile loaded TRANSPOSED via X's symmetry: Xs_t[k][r] = X[k][row0+r]
// (column k of X == row k) -> coalesced GMEM, conflict-free float4 smem reads.
__global__ __launch_bounds__(224) void k_xm(const float* __restrict__ X) {
    __shared__ float Xs_t[KC][RT];   // [k][row]
    __shared__ float Ms[KC][NP];     // [k][col]
    int b = blockIdx.y;
    int row0 = blockIdx.x * RT;
    int tid = threadIdx.x;
    int tx = tid % 14;   // col group (4 cols)
    int ty = tid / 14;   // row group (4 rows), 0..15
    const float* Xb = X + (size_t)b * N0 * N0;
    float* Yb = g_Y + (size_t)b * N0 * NP;
    float2 acc[4][2] = {};
    for (int kc = 0; kc < N0; kc += KC) {
        // Xs_t: 40x64 floats = 640 float4
        for (int l = tid; l < (KC * RT) / 4; l += 224) {
            int kk = l / (RT / 4), c4 = l - (l / (RT / 4)) * (RT / 4);
            int col = row0 + c4 * 4;
            float4 v = make_float4(0.f, 0.f, 0.f, 0.f);
            if (col < N0)
                v = *(const float4*)(Xb + (size_t)(kc + kk) * N0 + col);
            *(float4*)&Xs_t[kk][c4 * 4] = v;
        }
        // Ms: 40x56 floats = 560 float4
        for (int l = tid; l < (KC * NP) / 4; l += 224) {
            int kk = l / (NP / 4), c4 = l - (l / (NP / 4)) * (NP / 4);
            *(float4*)&Ms[kk][c4 * 4] = *(const float4*)(g_M + (kc + kk) * NP + c4 * 4);
        }
        __syncthreads();
#pragma unroll 8
        for (int kk = 0; kk < KC; kk++) {
            float4 av = *(float4*)&Xs_t[kk][ty * 4];
            float4 bv = *(float4*)&Ms[kk][tx * 4];
            float2 b0 = make_float2(bv.x, bv.y);
            float2 b1 = make_float2(bv.z, bv.w);
            ffma2(acc[0][0], make_float2(av.x, av.x), b0);
            ffma2(acc[0][1], make_float2(av.x, av.x), b1);
            ffma2(acc[1][0], make_float2(av.y, av.y), b0);
            ffma2(acc[1][1], make_float2(av.y, av.y), b1);
            ffma2(acc[2][0], make_float2(av.z, av.z), b0);
            ffma2(acc[2][1], make_float2(av.z, av.z), b1);
            ffma2(acc[3][0], make_float2(av.w, av.w), b0);
            ffma2(acc[3][1], make_float2(av.w, av.w), b1);
        }
        __syncthreads();
    }
#pragma unroll
    for (int r = 0; r < 4; r++) {
        int row = row0 + ty * 4 + r;
        if (row < N0) {
            float4 v = make_float4(acc[r][0].x, acc[r][0].y, acc[r][1].x, acc[r][1].y);
            *(float4*)(Yb + (size_t)row * NP + tx * 4) = v;
        }
    }
}

// map linear upper-triangular index t (triu_indices(50) row-major) -> (i,j)
__device__ __forceinline__ void tri_ij(int t, int& i, int& j) {
    int ii = (int)((101.0f - sqrtf(10201.0f - 8.0f * (float)t)) * 0.5f);
    if (ii < 0) ii = 0;
    if (ii > 49) ii = 49;
    while (ii > 0 && ii * (101 - ii) / 2 > t) ii--;
    while (ii < 49 && (ii + 1) * (100 - ii) / 2 <= t) ii++;
    i = ii;
    j = ii + t - ii * (101 - ii) / 2;
}

// ---------------- K3: h = M^T Y, S = log(h) via Chebyshev/Clenshaw, head ----------------
// One batch per 256-thread block (grid 256 -> all SMs covered).
// Matmuls on 125 threads, microtile 2 rows x 5 float2-cols (f32x2).
__global__ __launch_bounds__(256) void k_poly(const float* __restrict__ Wl,
                                              const float* __restrict__ bl,
                                              float* __restrict__ out) {
    __shared__ float sTs[NT * LDA];     // h, then Ts
    __shared__ float sP0[NT * LDB];     // Clenshaw buf / staging M
    __shared__ float sP1[NT * LDB];     // Clenshaw buf / staging Y
    __shared__ float s_row[NT];
    __shared__ float s_bb;
    __shared__ float s_red[7 * 8];

    int b = blockIdx.x;
    int tid = threadIdx.x;
    const float* Yb = g_Y + (size_t)b * N0 * NP;

    int rg = tid / 5;             // 0..24 (valid when tid<125)
    int cg = tid - rg * 5;        // 0..4
    int i0 = 2 * rg;
    int j0 = 10 * cg;

    // ---- h = M^T Y : 125 threads, 2x10 microtile, K staged in 50-row chunks ----
    float2 h0[5] = {}, h1[5] = {};
    for (int kc = 0; kc < N0; kc += NT) {
        for (int l = tid; l < NT * NT; l += 256) {
            int r = l / NT, c = l - (l / NT) * NT;
            sP0[r * LDB + c] = g_M[(kc + r) * NP + c];
            sP1[r * LDB + c] = Yb[(kc + r) * NP + c];
        }
        __syncthreads();
        if (tid < 125) {
#pragma unroll 5
            for (int kk = 0; kk < NT; kk++) {
                float m0 = sP0[kk * LDB + i0], m1 = sP0[kk * LDB + i0 + 1];
                float2 a0 = make_float2(m0, m0), a1 = make_float2(m1, m1);
#pragma unroll
                for (int j = 0; j < 5; j++) {
                    float2 yv = *(float2*)&sP1[kk * LDB + j0 + 2 * j];
                    ffma2(h0[j], a0, yv);
                    ffma2(h1[j], a1, yv);
                }
            }
        }
        __syncthreads();
    }
    if (tid < 125) {
#pragma unroll
        for (int j = 0; j < 5; j++) {
            sTs[i0 * LDA + j0 + 2 * j] = h0[j].x;
            sTs[i0 * LDA + j0 + 2 * j + 1] = h0[j].y;
            sTs[(i0 + 1) * LDA + j0 + 2 * j] = h1[j].x;
            sTs[(i0 + 1) * LDA + j0 + 2 * j + 1] = h1[j].y;
        }
    }
    __syncthreads();

    // ---- Gershgorin upper bound (spectrum lower bound ~1 by construction) ----
    if (tid < NT) {
        float s = 0.f;
        for (int j = 0; j < NT; j++) s += fabsf(sTs[tid * LDA + j]);
        s_row[tid] = s;
    }
    __syncthreads();
    if (tid == 0) {
        float mx = 0.f;
        for (int i = 0; i < NT; i++) mx = fmaxf(mx, s_row[i]);
        s_bb = mx;
    }
    __syncthreads();
    float aa = 0.95f, bb = s_bb;
    float mid = 0.5f * (aa + bb);
    float kap = (bb - aa) / (bb + aa);
    float z = (1.f - sqrtf(fmaxf(1.f - kap * kap, 0.f))) / kap;
    float c0 = logf(mid) - logf(1.f + z * z);

    // ---- Ts = (2h - (a+b)I)/(b-a); zero Clenshaw buffers ----
    {
        float inv = 1.f / (bb - aa);
        for (int l = tid; l < NT * NT; l += 256) {
            int i = l / NT, j = l - (l / NT) * NT;
            sTs[i * LDA + j] = (2.f * sTs[i * LDA + j] - (i == j ? (aa + bb) : 0.f)) * inv;
            sP0[i * LDB + j] = 0.f;
            sP1[i * LDB + j] = 0.f;
        }
    }
    __syncthreads();

    // ---- Clenshaw: B_k = c_k I + 2 Ts B_{k+1} - B_{k+2} ----
    float* pb1 = sP0;
    float* pb2 = sP1;
    for (int k = CHEB_D; k >= 0; k--) {
        float ck;
        float m2, m1c;  // new = m2*prod + m1c*(-pb2) + ck I
        if (k >= 1) {
            ck = 2.f * __powf(z, (float)k) / (float)k;
            if (!(k & 1)) ck = -ck;
            m2 = 2.f;
        } else {
            ck = c0;
            m2 = 1.f;
        }
        m1c = 1.f;
        if (tid < 125) {
            float2 p0[5] = {}, p1[5] = {};
#pragma unroll 5
            for (int kk = 0; kk < NT; kk++) {
                float t0 = sTs[i0 * LDA + kk], t1 = sTs[(i0 + 1) * LDA + kk];
                float2 a0 = make_float2(t0, t0), a1 = make_float2(t1, t1);
#pragma unroll
                for (int j = 0; j < 5; j++) {
                    float2 bv = *(float2*)&pb1[kk * LDB + j0 + 2 * j];
                    ffma2(p0[j], a0, bv);
                    ffma2(p1[j], a1, bv);
                }
            }
#pragma unroll
            for (int j = 0; j < 5; j++) {
                int jj = j0 + 2 * j;
                float2 o0 = *(float2*)&pb2[i0 * LDB + jj];
                float2 o1 = *(float2*)&pb2[(i0 + 1) * LDB + jj];
                float2 n0, n1;
                n0.x = m2 * p0[j].x - o0.x + (i0 == jj ? ck : 0.f);
                n0.y = m2 * p0[j].y - o0.y + (i0 == jj + 1 ? ck : 0.f);
                n1.x = m2 * p1[j].x - o1.x + (i0 + 1 == jj ? ck : 0.f);
                n1.y = m2 * p1[j].y - o1.y + (i0 + 1 == jj + 1 ? ck : 0.f);
                *(float2*)&pb2[i0 * LDB + jj] = n0;
                *(float2*)&pb2[(i0 + 1) * LDB + jj] = n1;
            }
        }
        __syncthreads();
        float* tmp = pb1; pb1 = pb2; pb2 = tmp;
    }
    // after the k==0 iteration + swap, S lives in pb1
    float* S = pb1;

    // ---- feat (1275 upper-tri, sqrt2 off-diag) fused into 7-dim head ----
    float po[7] = {0, 0, 0, 0, 0, 0, 0};
    for (int t = tid; t < NFEAT; t += 256) {
        int i, j;
        tri_ij(t, i, j);
        float s = S[i * LDB + j];
        float f = (i == j) ? s : s * 1.41421356237f;
#pragma unroll
        for (int c = 0; c < 7; c++) po[c] += f * Wl[c * NFEAT + t];
    }
    int lane = tid & 31, warp = tid >> 5;
#pragma unroll
    for (int off = 16; off > 0; off >>= 1) {
#pragma unroll
        for (int c = 0; c < 7; c++) po[c] += __shfl_down_sync(0xffffffffu, po[c], off);
    }
    if (lane == 0) {
#pragma unroll
        for (int c = 0; c < 7; c++) s_red[c * 8 + warp] = po[c];
    }
    __syncthreads();
    if (tid < 7) {
        float sum = bl[tid];
#pragma unroll
        for (int w = 0; w < 8; w++) sum += s_red[tid * 8 + w];
        out[b * 7 + tid] = sum;
    }
}

extern "C" void kernel_launch(void* const* d_in, const int* in_sizes, int n_in,
                              void* d_out, int out_size) {
    const float* x  = (const float*)d_in[0];
    const float* W1 = (const float*)d_in[1];
    const float* W2 = (const float*)d_in[2];
    const float* W3 = (const float*)d_in[3];
    const float* Wl = (const float*)d_in[4];
    const float* bl = (const float*)d_in[5];
    float* out = (float*)d_out;

    k_w2w3<<<40, 256>>>(W2, W3);
    k_w1t<<<88, 256>>>(W1);
    k_xm<<<dim3(7, BATCH), 224>>>(x);
    k_poly<<<BATCH, 256>>>(Wl, bl, out);
}